// round 17
// baseline (speedup 1.0000x reference)
#include <cuda_runtime.h>
#include <cstdint>

#define NXX 64
#define DTT 1e-4f

__device__ __forceinline__ float tanh_approx(float x) {
    float t;
    asm("tanh.approx.f32 %0, %1;" : "=f"(t) : "f"(x));
    return t;
}
__device__ __forceinline__ uint64_t pack2(float lo, float hi) {
    uint64_t r;
    asm("mov.b64 %0, {%1, %2};" : "=l"(r) : "f"(lo), "f"(hi));
    return r;
}
__device__ __forceinline__ void unpack2(uint64_t v, float& lo, float& hi) {
    asm("mov.b64 {%0, %1}, %2;" : "=f"(lo), "=f"(hi) : "l"(v));
}
__device__ __forceinline__ uint64_t fma2(uint64_t a, uint64_t b, uint64_t c) {
    uint64_t d;
    asm("fma.rn.f32x2 %0, %1, %2, %3;" : "=l"(d) : "l"(a), "l"(b), "l"(c));
    return d;
}

// 128 threads: 2 lanes per grid point (p = tid>>1, s = tid&1); lane s owns
// one full 16-unit layer as 8 f32x2 pairs (scalar f32 tanh on MUFU).
//
// BARRIER-FREE TAGGED EXCHANGE: per point a 16B slot {v0,tag0,v1,tag1} in a
// parity double buffer. Producer lane stores {v, it+1} as ONE atomic STS.64
// (tag rides with the data: no fence, no flag, no __syncthreads). Consumer
// issues both neighbor LDS.128 optimistically, overlaps uc/zb/cb in the LDS
// window, then checks the 4 tags and retries only if stale.
// Safety: warp A publishes tag t+1 only after reading neighbor B's tag t,
// which B published only after consuming A's tag t-1 => lag <= 1 step, so
// parity-2 buffering never clobbers an unread value. Own-warp slots are
// always current (same-warp LSU program order).
//
// PROGRESSIVE SUM (R16): S = fma2(Cq_j, t_j, S) seeded with basen (lane 0).
// uc = val + Poth from registers (shfl drains under the store window).
// Boundary (p=0,63): Cq=0 and basen=0 => un == 0.
// Stencil folded into weights (f64 at init): z = Wuc*uc + Wp*up + Wm*um + B,
//   Wp = 31.5*Wg + 3969*Wl, Wm = -31.5*Wg + 3969*Wl, Wuc = Wu - 7938*Wl.
// Head folded: Cq = gamma*DT*wc, Kc = gamma*DT*bc.
__global__ __launch_bounds__(128, 1) void scct_kernel(
    const float* __restrict__ u0,  const float* __restrict__ w1,
    const float* __restrict__ b1,  const float* __restrict__ w2,
    const float* __restrict__ b2,  const float* __restrict__ wc,
    const float* __restrict__ bc,  const float* __restrict__ gamma_p,
    const int*   __restrict__ nt_p, float* __restrict__ out)
{
    __shared__ uint4 ab[2][NXX];   // {v0, tag0, v1, tag1} per point
    __shared__ float uf[NXX];

    const int tid = threadIdx.x;
    const int p = tid >> 1;   // grid point 0..63
    const int s = tid & 1;    // layer select

    const float* wsel = s ? w2 : w1;
    const float* bsel = s ? b2 : b1;

    const float gmm = *gamma_p;
    const float gdt = gmm * DTT;
    const bool interior = (p > 0) && (p < NXX - 1);

    uint64_t Wp2[8], Wm2[8], Wuc2[8], Bq2[8], Cq2[8];
#pragma unroll
    for (int j = 0; j < 8; j++) {
        float pl[2], ml[2], ul[2], bl[2], cl[2];
#pragma unroll
        for (int h = 0; h < 2; h++) {
            int q = 2 * j + h;
            double Wu = (double)wsel[q * 3 + 0];
            double Wg = (double)wsel[q * 3 + 1];
            double Wl = (double)wsel[q * 3 + 2];
            if (interior) {
                pl[h] = (float)( 31.5 * Wg + 3969.0 * Wl);
                ml[h] = (float)(-31.5 * Wg + 3969.0 * Wl);
                ul[h] = (float)(Wu - 7938.0 * Wl);
                cl[h] = gdt * wc[s * 16 + q];
            } else {
                pl[h] = 0.0f;
                ml[h] = 0.0f;
                ul[h] = (float)Wu;
                cl[h] = 0.0f;             // boundary: P contributions vanish
            }
            bl[h] = bsel[q];
        }
        Wp2[j]  = pack2(pl[0], pl[1]);
        Wm2[j]  = pack2(ml[0], ml[1]);
        Wuc2[j] = pack2(ul[0], ul[1]);
        Bq2[j]  = pack2(bl[0], bl[1]);
        Cq2[j]  = pack2(cl[0], cl[1]);
    }
    const float Kc = gdt * (*bc);
    const int Nt = *nt_p;

    const float INVDX2 = 3969.0f;  // 63^2
    const int pm = (p == 0) ? 0 : p - 1;
    const int pp = (p == NXX - 1) ? NXX - 1 : p + 1;

    // SMEM addresses (32-bit shared window)
    const uint32_t own0 = (uint32_t)__cvta_generic_to_shared(&ab[0][p]) + s * 8;
    const uint32_t own1 = (uint32_t)__cvta_generic_to_shared(&ab[1][p]) + s * 8;
    const uint32_t am0  = (uint32_t)__cvta_generic_to_shared(&ab[0][pm]);
    const uint32_t am1  = (uint32_t)__cvta_generic_to_shared(&ab[1][pm]);
    const uint32_t ap0  = (uint32_t)__cvta_generic_to_shared(&ab[0][pp]);
    const uint32_t ap1  = (uint32_t)__cvta_generic_to_shared(&ab[1][pp]);

    // init: buffer 0 holds u0 with tag 0
    float val  = (s == 0) ? u0[p] : 0.0f;
    float Poth = (s == 0) ? 0.0f : u0[p];
    asm volatile("st.volatile.shared.v2.u32 [%0], {%1, %2};"
                 :: "r"(own0), "r"(__float_as_uint(val)), "r"(0u));
    __syncthreads();   // one-time: init visible everywhere

#pragma unroll 2
    for (int it = 0; it < Nt; ++it) {
        const uint32_t rtag = (uint32_t)it;          // expected tag this step
        const uint32_t amc = (it & 1) ? am1 : am0;
        const uint32_t apc = (it & 1) ? ap1 : ap0;
        const uint32_t ownN = (it & 1) ? own0 : own1;  // next-buffer own slot

        // ---- optimistic neighbor reads (chain head, LDS.128) ----
        uint32_t mv0, mt0, mv1, mt1, pv0, pt0, pv1, pt1;
        asm volatile("ld.volatile.shared.v4.u32 {%0,%1,%2,%3}, [%4];"
                     : "=r"(mv0), "=r"(mt0), "=r"(mv1), "=r"(mt1) : "r"(amc));
        asm volatile("ld.volatile.shared.v4.u32 {%0,%1,%2,%3}, [%4];"
                     : "=r"(pv0), "=r"(pt0), "=r"(pv1), "=r"(pt1) : "r"(apc));

        // ---- uc/zb/cb from registers: fills the LDS window ----
        const float uc = val + Poth;           // == consumers' v0+v1 bitwise
        const uint64_t uc2 = pack2(uc, uc);
        uint64_t zb2[8];
#pragma unroll
        for (int j = 0; j < 8; j++) zb2[j] = fma2(Wuc2[j], uc2, Bq2[j]);
        const float cb = fmaf(0.5f, uc, -(uc * uc * uc));   // 0.5u - u^3

        // ---- tag check; retry only if a neighbor warp lags ----
        bool ok = (mt0 == rtag) & (mt1 == rtag) & (pt0 == rtag) & (pt1 == rtag);
        while (!__all_sync(0xffffffffu, ok)) {
            asm volatile("ld.volatile.shared.v4.u32 {%0,%1,%2,%3}, [%4];"
                         : "=r"(mv0), "=r"(mt0), "=r"(mv1), "=r"(mt1) : "r"(amc));
            asm volatile("ld.volatile.shared.v4.u32 {%0,%1,%2,%3}, [%4];"
                         : "=r"(pv0), "=r"(pt0), "=r"(pv1), "=r"(pt1) : "r"(apc));
            ok = (mt0 == rtag) & (mt1 == rtag) & (pt0 == rtag) & (pt1 == rtag);
        }

        // neighbor u recon: ONE add each (same order as producers' val+Poth)
        const float um = __uint_as_float(mv0) + __uint_as_float(mv1);
        const float up = __uint_as_float(pv0) + __uint_as_float(pv1);
        const uint64_t um2 = pack2(um, um);
        const uint64_t up2 = pack2(up, up);

        // basen early (hidden under the MUFU drain)
        const float lx    = ((up - 2.0f * uc) + um) * INVDX2;
        const float core  = fmaf(0.8f, lx, cb);
        const float basen = interior ? (fmaf(DTT, core, uc) + Kc) : 0.0f;

        // ---- MLP: 8 f32x2 pairs, progressive sum seeded with basen ----
        uint64_t S = pack2((s == 0) ? basen : 0.0f, 0.0f);
#pragma unroll
        for (int j = 0; j < 8; j++) {
            uint64_t z2 = fma2(Wp2[j], up2, fma2(Wm2[j], um2, zb2[j]));
            float zl, zh;
            unpack2(z2, zl, zh);
            uint64_t t2 = pack2(tanh_approx(zl), tanh_approx(zh));
            S = fma2(Cq2[j], t2, S);
        }
        float Sl, Sh;
        unpack2(S, Sl, Sh);
        const float v = Sl + Sh;   // lane 0: basen+P0, lane 1: P1

        // ---- publish {v, it+1} atomically; shfl overlaps the store ----
        asm volatile("st.volatile.shared.v2.u32 [%0], {%1, %2};"
                     :: "r"(ownN), "r"(__float_as_uint(v)), "r"(rtag + 1u));
        const float oth = __shfl_xor_sync(0xffffffffu, v, 1);

        val = v;
        Poth = oth;
    }

    // ---- epilogue: all warps did exactly Nt steps; re-converge once ----
    if (s == 0) uf[p] = val + Poth;
    __syncthreads();
    if (tid < NXX) out[tid] = uf[tid];

    if (tid == 0) {
        float s2 = 0.0f, vmax = 0.0f;
        for (int i = 0; i < NXX; i++) {
            float u = uf[i];
            s2 += u * u;
            vmax = fmaxf(vmax, fabsf(u));
        }
        float phi2 = s2 * (1.0f / 64.0f);

        int hist[64];
#pragma unroll
        for (int i = 0; i < 64; i++) hist[i] = 0;
        float denom = fmaxf(vmax, 1e-12f);
        for (int i = 0; i < NXX; i++) {
            float vn = fabsf(uf[i]) / denom;   // IEEE div, matches ref
            int b = (int)(vn * 64.0f);
            if (b > 63) b = 63;
            hist[b]++;
        }
        float H = 0.0f;
        for (int i = 0; i < 64; i++) {
            if (hist[i] > 0) {
                float pb = (float)hist[i] * (1.0f / 64.0f);
                H -= pb * logf(pb);
            }
        }
        if (vmax < 1e-12f) H = 0.0f;
        out[64] = phi2;
        out[65] = H;
    }
}

extern "C" void kernel_launch(void* const* d_in, const int* in_sizes, int n_in,
                              void* d_out, int out_size) {
    (void)in_sizes; (void)n_in; (void)out_size;
    scct_kernel<<<1, 128>>>(
        (const float*)d_in[0],  // u0
        (const float*)d_in[1],  // w1
        (const float*)d_in[2],  // b1
        (const float*)d_in[3],  // w2
        (const float*)d_in[4],  // b2
        (const float*)d_in[5],  // wc
        (const float*)d_in[6],  // bc
        (const float*)d_in[7],  // gamma
        (const int*)  d_in[8],  // Nt
        (float*)d_out);
}